// round 14
// baseline (speedup 1.0000x reference)
#include <cuda_runtime.h>
#include <cuda_fp16.h>
#include <math.h>
#include <stdint.h>

// Problem sizes (fixed)
#define BATCH 8
#define SEQ   2048
#define DIM   1024
#define MTOT  (BATCH*SEQ)
#define PLANE (SEQ*DIM)
#define TEN   ((size_t)BATCH*PLANE)

// ---------------- device scratch (no allocations allowed) -------------------
__device__ float  g_scores[(size_t)BATCH * SEQ * SEQ];  // fp32 raw scores (S)
__device__ __half g_Ph[(size_t)BATCH * SEQ * SEQ];      // fp16 UNNORMALIZED exp (E)
__device__ float  g_inv[(size_t)BATCH * SEQ];           // 1/rowsum for PV epilogue
__device__ __half g_Wh[(size_t)3 * DIM * DIM];          // fp16 W^T [n][k]
__device__ __half g_Vh[(size_t)BATCH * DIM * SEQ];      // fp16 V^T [n][k]
__device__ __half g_Xh[(size_t)MTOT * DIM];             // fp16 X
__device__ __half g_Qh[(size_t)MTOT * DIM];             // fp16 Q
__device__ __half g_Kh[(size_t)MTOT * DIM];             // fp16 K

// ---------------- helpers ----------------------------------------------------
__device__ __forceinline__ uint32_t smem_u32(const void* p) {
    uint32_t a;
    asm("{ .reg .u64 t; cvta.to.shared.u64 t, %1; cvt.u32.u64 %0, t; }" : "=r"(a) : "l"(p));
    return a;
}
__device__ __forceinline__ void cp16(uint32_t s, const void* g) {
    asm volatile("cp.async.cg.shared.global [%0], [%1], 16;" :: "r"(s), "l"(g));
}
__device__ __forceinline__ void cp_commit() { asm volatile("cp.async.commit_group;" ::: "memory"); }
template <int N> __device__ __forceinline__ void cp_wait() {
    asm volatile("cp.async.wait_group %0;" :: "n"(N) : "memory");
}
__device__ __forceinline__ void mma_f16(float* c, const uint32_t* a, const uint32_t* b) {
    asm volatile(
        "mma.sync.aligned.m16n8k16.row.col.f32.f16.f16.f32 "
        "{%0,%1,%2,%3}, {%4,%5,%6,%7}, {%8,%9}, {%0,%1,%2,%3};"
        : "+f"(c[0]), "+f"(c[1]), "+f"(c[2]), "+f"(c[3])
        : "r"(a[0]), "r"(a[1]), "r"(a[2]), "r"(a[3]), "r"(b[0]), "r"(b[1]));
}
__device__ __forceinline__ uint32_t ex2_h2(uint32_t a) {   // 2 x 2^x on halves
    uint32_t d;
    asm("ex2.approx.f16x2 %0, %1;" : "=r"(d) : "r"(a));
    return d;
}

// ---------------- GEMM config ------------------------------------------------
#define BM 128
#define BN 128
#define BKH 32                   // K halfs per stage
#define PITCH_H 40               // half pitch; conflict-free fragment LDS
#define STAGES 3
#define ASTG (BM*PITCH_H)
#define BSTG (BN*PITCH_H)
#define SMEM_TOTAL (STAGES*(ASTG+BSTG)*2)   // 61,440 B -> 2 CTAs/SM

// 128 threads = 4 warps (2 along M x 2 along N), each owns a 64x64 sub-tile.
// MODE 0: QKV  C = Xh * Wh^T
// MODE 1: S    C = Qh * Kh^T (causal blocks, scaled)
// MODE 2: O    C = E  * Vh^T (causal K length; x 1/rowsum in epilogue)
template <int MODE>
__global__ __launch_bounds__(128, 2)
void gemm_tc(float* __restrict__ out)
{
    const int bx = blockIdx.x, by = blockIdx.y, bz = blockIdx.z;
    if (MODE == 1 && bx > by) return;

    const __half *A, *B;
    float *C;
    int lda, ldb, ldc, KT;
    float scale = 1.f;

    if (MODE == 0) {
        A = g_Xh + (size_t)by * BM * DIM;                           lda = DIM;
        B = g_Wh + (size_t)bz * DIM * DIM + (size_t)bx * BN * DIM;  ldb = DIM;
        C = out + (size_t)(1 + bz) * TEN + (size_t)by * BM * DIM + bx * BN; ldc = DIM;
        KT = DIM / BKH;
    } else if (MODE == 1) {
        A = g_Qh + (size_t)bz * PLANE + (size_t)by * BM * DIM;      lda = DIM;
        B = g_Kh + (size_t)bz * PLANE + (size_t)bx * BN * DIM;      ldb = DIM;
        C = g_scores + (size_t)bz * SEQ * SEQ + (size_t)by * BM * SEQ + bx * BN; ldc = SEQ;
        KT = DIM / BKH;
        scale = 0.03125f;   // 1/sqrt(1024)
    } else {
        A = g_Ph + (size_t)bz * SEQ * SEQ + (size_t)by * BM * SEQ;  lda = SEQ;
        B = g_Vh + (size_t)bz * DIM * SEQ + (size_t)bx * BN * SEQ;  ldb = SEQ;
        C = out + (size_t)bz * PLANE + (size_t)by * BM * DIM + bx * BN; ldc = DIM;
        KT = (by + 1) * (BM / BKH);
    }

    extern __shared__ __half sm[];
    const uint32_t sb = smem_u32(sm);
    const int tid = threadIdx.x;
    const int lane = tid & 31;
    const int warp = tid >> 5;
    const int warpM = warp & 1;       // 2 warps along M (64 rows)
    const int warpN = warp >> 1;      // 2 warps along N (64 cols)

    float acc[4][8][4];
#pragma unroll
    for (int mt = 0; mt < 4; mt++)
#pragma unroll
        for (int nt = 0; nt < 8; nt++)
#pragma unroll
            for (int i = 0; i < 4; i++) acc[mt][nt][i] = 0.f;

    auto load_stage = [&](int st, int k0) {
        const uint32_t sA = sb + (uint32_t)(st * ASTG) * 2;
        const uint32_t sB = sb + (uint32_t)((STAGES * ASTG) + st * BSTG) * 2;
#pragma unroll
        for (int i = 0; i < 4; i++) {
            int ci = tid + i * 128;
            int r = ci >> 2, ch = ci & 3;
            cp16(sA + (uint32_t)(r * PITCH_H + ch * 8) * 2, A + (size_t)r * lda + k0 + ch * 8);
        }
#pragma unroll
        for (int i = 0; i < 4; i++) {
            int ci = tid + i * 128;
            int r = ci >> 2, ch = ci & 3;
            cp16(sB + (uint32_t)(r * PITCH_H + ch * 8) * 2, B + (size_t)r * ldb + k0 + ch * 8);
        }
    };

#pragma unroll
    for (int p = 0; p < STAGES - 1; p++) {
        load_stage(p, p * BKH);
        cp_commit();
    }

    for (int it = 0; it < KT; ++it) {
        cp_wait<STAGES - 2>();
        __syncthreads();   // stage `it` ready AND all threads done with stage it-1

        // next load overwrites slot (it+STAGES-1)%STAGES == (it-1)%STAGES —
        // safe after the sync above (no trailing barrier needed).
        const int nx = it + STAGES - 1;
        if (nx < KT) load_stage(nx % STAGES, nx * BKH);
        cp_commit();

        const int s = it % STAGES;
        const __half* sAf = sm + s * ASTG;
        const __half* sBf = sm + STAGES * ASTG + s * BSTG;

#pragma unroll
        for (int k16 = 0; k16 < BKH / 16; k16++) {
            const int ch = k16 * 16 + 2 * (lane & 3);
            uint32_t af[4][4];
            uint32_t bf[8][2];
            const int r0 = warpM * 64 + (lane >> 2);
#pragma unroll
            for (int mt = 0; mt < 4; mt++) {
                const int rr = r0 + mt * 16;
                af[mt][0] = *(const uint32_t*)(sAf + rr * PITCH_H + ch);
                af[mt][1] = *(const uint32_t*)(sAf + (rr + 8) * PITCH_H + ch);
                af[mt][2] = *(const uint32_t*)(sAf + rr * PITCH_H + ch + 8);
                af[mt][3] = *(const uint32_t*)(sAf + (rr + 8) * PITCH_H + ch + 8);
            }
            const int n0 = warpN * 64 + (lane >> 2);
#pragma unroll
            for (int nt = 0; nt < 8; nt++) {
                const int nn = n0 + nt * 8;
                bf[nt][0] = *(const uint32_t*)(sBf + nn * PITCH_H + ch);
                bf[nt][1] = *(const uint32_t*)(sBf + nn * PITCH_H + ch + 8);
            }
#pragma unroll
            for (int mt = 0; mt < 4; mt++)
#pragma unroll
                for (int nt = 0; nt < 8; nt++)
                    mma_f16(acc[mt][nt], af[mt], bf[nt]);
        }
    }

    // ---- epilogue ----
    const int rbase = warpM * 64 + (lane >> 2);
    const int cbase = warpN * 64 + 2 * (lane & 3);
#pragma unroll
    for (int mt = 0; mt < 4; mt++) {
        const int row = rbase + mt * 16;
        float s0 = scale, s1 = scale;
        if (MODE == 2) {   // fold softmax 1/rowsum into the PV epilogue
            const float* inv = g_inv + (size_t)bz * SEQ + by * BM;
            s0 = inv[row];
            s1 = inv[row + 8];
        }
#pragma unroll
        for (int nt = 0; nt < 8; nt++) {
            const int col = cbase + nt * 8;
            float2 v0 = {acc[mt][nt][0] * s0, acc[mt][nt][1] * s0};
            float2 v1 = {acc[mt][nt][2] * s1, acc[mt][nt][3] * s1};
            *(float2*)(C + (size_t)row * ldc + col)       = v0;
            *(float2*)(C + (size_t)(row + 8) * ldc + col) = v1;

            if (MODE == 0 && bz < 2) {   // emit fp16 Q / K for the score GEMM
                __half* T = (bz == 0 ? g_Qh : g_Kh) +
                            (size_t)(by * BM + row) * DIM + bx * BN + col;
                *(__half2*)T = __floats2half2_rn(v0.x, v0.y);
                *(__half2*)(T + (size_t)8 * DIM) = __floats2half2_rn(v1.x, v1.y);
            }
        }
    }
}

// ---------------- producers --------------------------------------------------
__global__ __launch_bounds__(256)
void cvt_x(const float* __restrict__ X)
{
    size_t i = ((size_t)blockIdx.x * 256 + threadIdx.x) * 4;
    float4 v = *(const float4*)(X + i);
    *(__half2*)(g_Xh + i)     = __floats2half2_rn(v.x, v.y);
    *(__half2*)(g_Xh + i + 2) = __floats2half2_rn(v.z, v.w);
}

__global__ __launch_bounds__(256)
void transpose_w(const float* __restrict__ Wq, const float* __restrict__ Wk,
                 const float* __restrict__ Wv)
{
    __shared__ float t[32][33];
    const int w = blockIdx.z;
    const float* W = (w == 0) ? Wq : (w == 1) ? Wk : Wv;
    __half* Wh = g_Wh + (size_t)w * DIM * DIM;
    const int n0 = blockIdx.x * 32, k0 = blockIdx.y * 32;
    const int tx = threadIdx.x & 31, ty = threadIdx.x >> 5;
#pragma unroll
    for (int j = 0; j < 4; j++)
        t[ty * 4 + j][tx] = W[(size_t)(k0 + ty * 4 + j) * DIM + n0 + tx];
    __syncthreads();
#pragma unroll
    for (int j = 0; j < 4; j++)
        Wh[(size_t)(n0 + ty * 4 + j) * DIM + k0 + tx] = __float2half_rn(t[tx][ty * 4 + j]);
}

__global__ __launch_bounds__(256)
void transpose_v(const float* __restrict__ out)
{
    __shared__ float t[32][33];
    const int b = blockIdx.z;
    const float* V = out + 3 * TEN + (size_t)b * PLANE;   // [S][D] fp32
    __half* Vh = g_Vh + (size_t)b * DIM * SEQ;            // [D][S] fp16
    const int s0 = blockIdx.x * 32, a0 = blockIdx.y * 32;
    const int tx = threadIdx.x & 31, ty = threadIdx.x >> 5;
#pragma unroll
    for (int j = 0; j < 4; j++)
        t[ty * 4 + j][tx] = V[(size_t)(s0 + ty * 4 + j) * DIM + a0 + tx];
    __syncthreads();
#pragma unroll
    for (int j = 0; j < 4; j++)
        Vh[(size_t)(a0 + ty * 4 + j) * SEQ + s0 + tx] = __float2half_rn(t[tx][ty * 4 + j]);
}

// ---------------- softmax: E = exp(s - max) in fp16 (unnormalized),
//                  1/rowsum -> g_inv (applied in PV epilogue) -----------------
#define LOG2E 1.44269504088896340736f
__global__ __launch_bounds__(256)
void softmax_rows()
{
    __shared__ float row[SEQ];
    __shared__ float red[8];
    const int q = blockIdx.x, b = blockIdx.y, tid = threadIdx.x;
    const int lane = tid & 31, warp = tid >> 5;
    const float* Srow = g_scores + (size_t)b * SEQ * SEQ + (size_t)q * SEQ;
    __half* Prow = g_Ph + (size_t)b * SEQ * SEQ + (size_t)q * SEQ;
    const int L = q + 1;
    const int kend = ((q >> 7) + 1) << 7;
    const int L4 = L >> 2;

    float mx = -INFINITY;
    const float4* S4 = (const float4*)Srow;
    for (int i = tid; i < L4; i += 256) {
        float4 v = S4[i];
        *(float4*)&row[i * 4] = v;
        mx = fmaxf(fmaxf(mx, fmaxf(v.x, v.y)), fmaxf(v.z, v.w));
    }
    if (L4 * 4 + tid < L) {
        float v = Srow[L4 * 4 + tid];
        row[L4 * 4 + tid] = v;
        mx = fmaxf(mx, v);
    }
#pragma unroll
    for (int o = 16; o > 0; o >>= 1) mx = fmaxf(mx, __shfl_xor_sync(~0u, mx, o));
    if (lane == 0) red[warp] = mx;
    __syncthreads();
    mx = red[0];
#pragma unroll
    for (int w2 = 1; w2 < 8; w2++) mx = fmaxf(mx, red[w2]);
    __syncthreads();

    // single exp pass: y = (s-mx)*log2e <= 0, 2^y via f16x2 MUFU (2 per op)
    float sum = 0.f;
    for (int i = tid; i < L4; i += 256) {
        float4 v = *(float4*)&row[i * 4];
        __half2 y0 = __floats2half2_rn((v.x - mx) * LOG2E, (v.y - mx) * LOG2E);
        __half2 y1 = __floats2half2_rn((v.z - mx) * LOG2E, (v.w - mx) * LOG2E);
        uint32_t e0 = ex2_h2(*(uint32_t*)&y0);
        uint32_t e1 = ex2_h2(*(uint32_t*)&y1);
        *(uint32_t*)(Prow + i * 4)     = e0;
        *(uint32_t*)(Prow + i * 4 + 2) = e1;
        __half2 h0 = *(__half2*)&e0;
        __half2 h1 = *(__half2*)&e1;
        sum += __low2float(h0) + __high2float(h0) + __low2float(h1) + __high2float(h1);
    }
    if (L4 * 4 + tid < L) {
        const int j = L4 * 4 + tid;
        __half2 y = __floats2half2_rn((row[j] - mx) * LOG2E, -100.f);
        uint32_t e = ex2_h2(*(uint32_t*)&y);
        __half2 h = *(__half2*)&e;
        Prow[j] = __low2half(h);
        sum += __low2float(h);
    }
#pragma unroll
    for (int o = 16; o > 0; o >>= 1) sum += __shfl_xor_sync(~0u, sum, o);
    if (lane == 0) red[warp] = sum;
    __syncthreads();
    sum = 0.f;
#pragma unroll
    for (int w2 = 0; w2 < 8; w2++) sum += red[w2];
    if (tid == 0) g_inv[(size_t)b * SEQ + q] = 1.f / sum;

    for (int i = L + tid; i < kend; i += 256) Prow[i] = __ushort_as_half((unsigned short)0);
}

// ---------------- launch -----------------------------------------------------
extern "C" void kernel_launch(void* const* d_in, const int* in_sizes, int n_in,
                              void* d_out, int out_size)
{
    const float* X  = (const float*)d_in[0];
    const float* Wq = (const float*)d_in[1];
    const float* Wk = (const float*)d_in[2];
    const float* Wv = (const float*)d_in[3];
    float* out = (float*)d_out;

    static bool attr_done = false;
    if (!attr_done) {
        cudaFuncSetAttribute(gemm_tc<0>, cudaFuncAttributeMaxDynamicSharedMemorySize, SMEM_TOTAL);
        cudaFuncSetAttribute(gemm_tc<1>, cudaFuncAttributeMaxDynamicSharedMemorySize, SMEM_TOTAL);
        cudaFuncSetAttribute(gemm_tc<2>, cudaFuncAttributeMaxDynamicSharedMemorySize, SMEM_TOTAL);
        attr_done = true;
    }

    cvt_x<<<(MTOT * (size_t)DIM) / (256 * 4), 256>>>(X);
    transpose_w<<<dim3(DIM / 32, DIM / 32, 3), 256>>>(Wq, Wk, Wv);
    gemm_tc<0><<<dim3(DIM / BN, MTOT / BM, 3), 128, SMEM_TOTAL>>>(out);
    transpose_v<<<dim3(SEQ / 32, DIM / 32, BATCH), 256>>>(out);
    gemm_tc<1><<<dim3(SEQ / BN, SEQ / BM, BATCH), 128, SMEM_TOTAL>>>(out);
    softmax_rows<<<dim3(SEQ, BATCH), 256>>>();
    gemm_tc<2><<<dim3(DIM / BN, SEQ / BM, BATCH), 128, SMEM_TOTAL>>>(out);
}

// round 15
// speedup vs baseline: 1.5526x; 1.5526x over previous
#include <cuda_runtime.h>
#include <cuda_fp16.h>
#include <math.h>
#include <stdint.h>

// Problem sizes (fixed)
#define BATCH 8
#define SEQ   2048
#define DIM   1024
#define MTOT  (BATCH*SEQ)
#define PLANE (SEQ*DIM)
#define TEN   ((size_t)BATCH*PLANE)

// ---------------- device scratch (no allocations allowed) -------------------
__device__ float  g_scores[(size_t)BATCH * SEQ * SEQ];  // fp32 raw scores (S)
__device__ __half g_Ph[(size_t)BATCH * SEQ * SEQ];      // fp16 UNNORMALIZED exp (E)
__device__ float  g_inv[(size_t)BATCH * SEQ];           // 1/rowsum for PV epilogue
__device__ __half g_Wh[(size_t)3 * DIM * DIM];          // fp16 W^T [n][k]
__device__ __half g_Vh[(size_t)BATCH * DIM * SEQ];      // fp16 V^T [n][k]
__device__ __half g_Xh[(size_t)MTOT * DIM];             // fp16 X
__device__ __half g_Qh[(size_t)MTOT * DIM];             // fp16 Q
__device__ __half g_Kh[(size_t)MTOT * DIM];             // fp16 K

// ---------------- helpers ----------------------------------------------------
__device__ __forceinline__ uint32_t smem_u32(const void* p) {
    uint32_t a;
    asm("{ .reg .u64 t; cvta.to.shared.u64 t, %1; cvt.u32.u64 %0, t; }" : "=r"(a) : "l"(p));
    return a;
}
__device__ __forceinline__ void cp16(uint32_t s, const void* g) {
    asm volatile("cp.async.cg.shared.global [%0], [%1], 16;" :: "r"(s), "l"(g));
}
__device__ __forceinline__ void cp_commit() { asm volatile("cp.async.commit_group;" ::: "memory"); }
template <int N> __device__ __forceinline__ void cp_wait() {
    asm volatile("cp.async.wait_group %0;" :: "n"(N) : "memory");
}
__device__ __forceinline__ void mma_f16(float* c, const uint32_t* a, const uint32_t* b) {
    asm volatile(
        "mma.sync.aligned.m16n8k16.row.col.f32.f16.f16.f32 "
        "{%0,%1,%2,%3}, {%4,%5,%6,%7}, {%8,%9}, {%0,%1,%2,%3};"
        : "+f"(c[0]), "+f"(c[1]), "+f"(c[2]), "+f"(c[3])
        : "r"(a[0]), "r"(a[1]), "r"(a[2]), "r"(a[3]), "r"(b[0]), "r"(b[1]));
}
__device__ __forceinline__ uint32_t ex2_h2(uint32_t a) {   // 2 x 2^x on halves
    uint32_t d;
    asm("ex2.approx.f16x2 %0, %1;" : "=r"(d) : "r"(a));
    return d;
}

// ---------------- GEMM config ------------------------------------------------
#define BM 128
#define BN 128
#define BKH 32                   // K halfs per stage
#define PITCH_H 40               // half pitch; conflict-free fragment LDS
#define STAGES 3
#define ASTG (BM*PITCH_H)
#define BSTG (BN*PITCH_H)
#define SMEM_TOTAL (STAGES*(ASTG+BSTG)*2)   // 61,440 B -> 2 CTAs/SM

// 128 threads = 4 warps (2 along M x 2 along N), each owns a 64x64 sub-tile.
// MODE 0: QKV  C = Xh * Wh^T
// MODE 1: S    C = Qh * Kh^T (causal blocks, scaled)
// MODE 2: O    C = E  * Vh^T (causal K length; x 1/rowsum in epilogue)
template <int MODE>
__global__ __launch_bounds__(128, 2)
void gemm_tc(float* __restrict__ out)
{
    const int bx = blockIdx.x, by = blockIdx.y, bz = blockIdx.z;
    if (MODE == 1 && bx > by) return;

    const __half *A, *B;
    float *C;
    int lda, ldb, ldc, KT;
    float scale = 1.f;

    if (MODE == 0) {
        A = g_Xh + (size_t)by * BM * DIM;                           lda = DIM;
        B = g_Wh + (size_t)bz * DIM * DIM + (size_t)bx * BN * DIM;  ldb = DIM;
        C = out + (size_t)(1 + bz) * TEN + (size_t)by * BM * DIM + bx * BN; ldc = DIM;
        KT = DIM / BKH;
    } else if (MODE == 1) {
        A = g_Qh + (size_t)bz * PLANE + (size_t)by * BM * DIM;      lda = DIM;
        B = g_Kh + (size_t)bz * PLANE + (size_t)bx * BN * DIM;      ldb = DIM;
        C = g_scores + (size_t)bz * SEQ * SEQ + (size_t)by * BM * SEQ + bx * BN; ldc = SEQ;
        KT = DIM / BKH;
        scale = 0.03125f;   // 1/sqrt(1024)
    } else {
        A = g_Ph + (size_t)bz * SEQ * SEQ + (size_t)by * BM * SEQ;  lda = SEQ;
        B = g_Vh + (size_t)bz * DIM * SEQ + (size_t)bx * BN * SEQ;  ldb = SEQ;
        C = out + (size_t)bz * PLANE + (size_t)by * BM * DIM + bx * BN; ldc = DIM;
        KT = (by + 1) * (BM / BKH);
    }

    extern __shared__ __half sm[];
    const uint32_t sb = smem_u32(sm);
    const int tid = threadIdx.x;
    const int lane = tid & 31;
    const int warp = tid >> 5;
    const int warpM = warp & 1;       // 2 warps along M (64 rows)
    const int warpN = warp >> 1;      // 2 warps along N (64 cols)

    float acc[4][8][4];
#pragma unroll
    for (int mt = 0; mt < 4; mt++)
#pragma unroll
        for (int nt = 0; nt < 8; nt++)
#pragma unroll
            for (int i = 0; i < 4; i++) acc[mt][nt][i] = 0.f;

    // Stage tile: rows x 32 halfs; 4 x 16B chunks per row.
    auto load_stage = [&](int st, int k0) {
        const uint32_t sA = sb + (uint32_t)(st * ASTG) * 2;
        const uint32_t sB = sb + (uint32_t)((STAGES * ASTG) + st * BSTG) * 2;
#pragma unroll
        for (int i = 0; i < 4; i++) {
            int ci = tid + i * 128;
            int r = ci >> 2, ch = ci & 3;
            cp16(sA + (uint32_t)(r * PITCH_H + ch * 8) * 2, A + (size_t)r * lda + k0 + ch * 8);
        }
#pragma unroll
        for (int i = 0; i < 4; i++) {
            int ci = tid + i * 128;
            int r = ci >> 2, ch = ci & 3;
            cp16(sB + (uint32_t)(r * PITCH_H + ch * 8) * 2, B + (size_t)r * ldb + k0 + ch * 8);
        }
    };

#pragma unroll
    for (int p = 0; p < STAGES - 1; p++) {
        load_stage(p, p * BKH);
        cp_commit();
    }

    for (int it = 0; it < KT; ++it) {
        cp_wait<STAGES - 2>();
        __syncthreads();

        const int nx = it + STAGES - 1;
        if (nx < KT) load_stage(nx % STAGES, nx * BKH);
        cp_commit();

        const int s = it % STAGES;
        const __half* sAf = sm + s * ASTG;
        const __half* sBf = sm + STAGES * ASTG + s * BSTG;

#pragma unroll
        for (int k16 = 0; k16 < BKH / 16; k16++) {
            const int ch = k16 * 16 + 2 * (lane & 3);
            uint32_t af[4][4];
            uint32_t bf[8][2];
            const int r0 = warpM * 64 + (lane >> 2);
#pragma unroll
            for (int mt = 0; mt < 4; mt++) {
                const int rr = r0 + mt * 16;
                af[mt][0] = *(const uint32_t*)(sAf + rr * PITCH_H + ch);
                af[mt][1] = *(const uint32_t*)(sAf + (rr + 8) * PITCH_H + ch);
                af[mt][2] = *(const uint32_t*)(sAf + rr * PITCH_H + ch + 8);
                af[mt][3] = *(const uint32_t*)(sAf + (rr + 8) * PITCH_H + ch + 8);
            }
            const int n0 = warpN * 64 + (lane >> 2);
#pragma unroll
            for (int nt = 0; nt < 8; nt++) {
                const int nn = n0 + nt * 8;
                bf[nt][0] = *(const uint32_t*)(sBf + nn * PITCH_H + ch);
                bf[nt][1] = *(const uint32_t*)(sBf + nn * PITCH_H + ch + 8);
            }
#pragma unroll
            for (int mt = 0; mt < 4; mt++)
#pragma unroll
                for (int nt = 0; nt < 8; nt++)
                    mma_f16(acc[mt][nt], af[mt], bf[nt]);
        }
        __syncthreads();
    }

    // ---- epilogue ----
    const int rbase = warpM * 64 + (lane >> 2);
    const int cbase = warpN * 64 + 2 * (lane & 3);
#pragma unroll
    for (int mt = 0; mt < 4; mt++) {
        const int row = rbase + mt * 16;
        float s0 = scale, s1 = scale;
        if (MODE == 2) {   // fold softmax 1/rowsum into the PV epilogue
            const float* inv = g_inv + (size_t)bz * SEQ + by * BM;
            s0 = inv[row];
            s1 = inv[row + 8];
        }
#pragma unroll
        for (int nt = 0; nt < 8; nt++) {
            const int col = cbase + nt * 8;
            float2 v0 = {acc[mt][nt][0] * s0, acc[mt][nt][1] * s0};
            float2 v1 = {acc[mt][nt][2] * s1, acc[mt][nt][3] * s1};
            *(float2*)(C + (size_t)row * ldc + col)       = v0;
            *(float2*)(C + (size_t)(row + 8) * ldc + col) = v1;

            if (MODE == 0 && bz < 2) {   // emit fp16 Q / K for the score GEMM
                __half* T = (bz == 0 ? g_Qh : g_Kh) +
                            (size_t)(by * BM + row) * DIM + bx * BN + col;
                *(__half2*)T = __floats2half2_rn(v0.x, v0.y);
                *(__half2*)(T + (size_t)8 * DIM) = __floats2half2_rn(v1.x, v1.y);
            }
        }
    }
}

// ---------------- producers --------------------------------------------------
__global__ __launch_bounds__(256)
void cvt_x(const float* __restrict__ X)
{
    size_t i = ((size_t)blockIdx.x * 256 + threadIdx.x) * 4;
    float4 v = *(const float4*)(X + i);
    *(__half2*)(g_Xh + i)     = __floats2half2_rn(v.x, v.y);
    *(__half2*)(g_Xh + i + 2) = __floats2half2_rn(v.z, v.w);
}

__global__ __launch_bounds__(256)
void transpose_w(const float* __restrict__ Wq, const float* __restrict__ Wk,
                 const float* __restrict__ Wv)
{
    __shared__ float t[32][33];
    const int w = blockIdx.z;
    const float* W = (w == 0) ? Wq : (w == 1) ? Wk : Wv;
    __half* Wh = g_Wh + (size_t)w * DIM * DIM;
    const int n0 = blockIdx.x * 32, k0 = blockIdx.y * 32;
    const int tx = threadIdx.x & 31, ty = threadIdx.x >> 5;
#pragma unroll
    for (int j = 0; j < 4; j++)
        t[ty * 4 + j][tx] = W[(size_t)(k0 + ty * 4 + j) * DIM + n0 + tx];
    __syncthreads();
#pragma unroll
    for (int j = 0; j < 4; j++)
        Wh[(size_t)(n0 + ty * 4 + j) * DIM + k0 + tx] = __float2half_rn(t[tx][ty * 4 + j]);
}

__global__ __launch_bounds__(256)
void transpose_v(const float* __restrict__ out)
{
    __shared__ float t[32][33];
    const int b = blockIdx.z;
    const float* V = out + 3 * TEN + (size_t)b * PLANE;   // [S][D] fp32
    __half* Vh = g_Vh + (size_t)b * DIM * SEQ;            // [D][S] fp16
    const int s0 = blockIdx.x * 32, a0 = blockIdx.y * 32;
    const int tx = threadIdx.x & 31, ty = threadIdx.x >> 5;
#pragma unroll
    for (int j = 0; j < 4; j++)
        t[ty * 4 + j][tx] = V[(size_t)(s0 + ty * 4 + j) * DIM + a0 + tx];
    __syncthreads();
#pragma unroll
    for (int j = 0; j < 4; j++)
        Vh[(size_t)(a0 + ty * 4 + j) * SEQ + s0 + tx] = __float2half_rn(t[tx][ty * 4 + j]);
}

// ---------------- softmax: E = exp(s - max) in fp16 (unnormalized),
//                  1/rowsum -> g_inv (applied in PV epilogue) -----------------
#define LOG2E 1.44269504088896340736f
__global__ __launch_bounds__(256)
void softmax_rows()
{
    __shared__ float row[SEQ];
    __shared__ float red[8];
    const int q = blockIdx.x, b = blockIdx.y, tid = threadIdx.x;
    const int lane = tid & 31, warp = tid >> 5;
    const float* Srow = g_scores + (size_t)b * SEQ * SEQ + (size_t)q * SEQ;
    __half* Prow = g_Ph + (size_t)b * SEQ * SEQ + (size_t)q * SEQ;
    const int L = q + 1;
    const int kend = ((q >> 7) + 1) << 7;
    const int L4 = L >> 2;

    float mx = -INFINITY;
    const float4* S4 = (const float4*)Srow;
    for (int i = tid; i < L4; i += 256) {
        float4 v = S4[i];
        *(float4*)&row[i * 4] = v;
        mx = fmaxf(fmaxf(mx, fmaxf(v.x, v.y)), fmaxf(v.z, v.w));
    }
    if (L4 * 4 + tid < L) {
        float v = Srow[L4 * 4 + tid];
        row[L4 * 4 + tid] = v;
        mx = fmaxf(mx, v);
    }
#pragma unroll
    for (int o = 16; o > 0; o >>= 1) mx = fmaxf(mx, __shfl_xor_sync(~0u, mx, o));
    if (lane == 0) red[warp] = mx;
    __syncthreads();
    mx = red[0];
#pragma unroll
    for (int w2 = 1; w2 < 8; w2++) mx = fmaxf(mx, red[w2]);
    __syncthreads();

    // single exp pass: y = (s-mx)*log2e <= 0, 2^y via f16x2 MUFU (2 per op)
    float sum = 0.f;
    for (int i = tid; i < L4; i += 256) {
        float4 v = *(float4*)&row[i * 4];
        __half2 y0 = __floats2half2_rn((v.x - mx) * LOG2E, (v.y - mx) * LOG2E);
        __half2 y1 = __floats2half2_rn((v.z - mx) * LOG2E, (v.w - mx) * LOG2E);
        uint32_t e0 = ex2_h2(*(uint32_t*)&y0);
        uint32_t e1 = ex2_h2(*(uint32_t*)&y1);
        *(uint32_t*)(Prow + i * 4)     = e0;
        *(uint32_t*)(Prow + i * 4 + 2) = e1;
        __half2 h0 = *(__half2*)&e0;
        __half2 h1 = *(__half2*)&e1;
        sum += __low2float(h0) + __high2float(h0) + __low2float(h1) + __high2float(h1);
    }
    if (L4 * 4 + tid < L) {
        const int j = L4 * 4 + tid;
        __half2 y = __floats2half2_rn((row[j] - mx) * LOG2E, -100.f);
        uint32_t e = ex2_h2(*(uint32_t*)&y);
        __half2 h = *(__half2*)&e;
        Prow[j] = __low2half(h);
        sum += __low2float(h);
    }
#pragma unroll
    for (int o = 16; o > 0; o >>= 1) sum += __shfl_xor_sync(~0u, sum, o);
    if (lane == 0) red[warp] = sum;
    __syncthreads();
    sum = 0.f;
#pragma unroll
    for (int w2 = 0; w2 < 8; w2++) sum += red[w2];
    if (tid == 0) g_inv[(size_t)b * SEQ + q] = 1.f / sum;

    for (int i = L + tid; i < kend; i += 256) Prow[i] = __ushort_as_half((unsigned short)0);
}

// ---------------- launch -----------------------------------------------------
extern "C" void kernel_launch(void* const* d_in, const int* in_sizes, int n_in,
                              void* d_out, int out_size)
{
    const float* X  = (const float*)d_in[0];
    const float* Wq = (const float*)d_in[1];
    const float* Wk = (const float*)d_in[2];
    const float* Wv = (const float*)d_in[3];
    float* out = (float*)d_out;

    static bool attr_done = false;
    if (!attr_done) {
        cudaFuncSetAttribute(gemm_tc<0>, cudaFuncAttributeMaxDynamicSharedMemorySize, SMEM_TOTAL);
        cudaFuncSetAttribute(gemm_tc<1>, cudaFuncAttributeMaxDynamicSharedMemorySize, SMEM_TOTAL);
        cudaFuncSetAttribute(gemm_tc<2>, cudaFuncAttributeMaxDynamicSharedMemorySize, SMEM_TOTAL);
        attr_done = true;
    }

    cvt_x<<<(MTOT * (size_t)DIM) / (256 * 4), 256>>>(X);
    transpose_w<<<dim3(DIM / 32, DIM / 32, 3), 256>>>(Wq, Wk, Wv);
    gemm_tc<0><<<dim3(DIM / BN, MTOT / BM, 3), 128, SMEM_TOTAL>>>(out);
    transpose_v<<<dim3(SEQ / 32, DIM / 32, BATCH), 256>>>(out);
    gemm_tc<1><<<dim3(SEQ / BN, SEQ / BM, BATCH), 128, SMEM_TOTAL>>>(out);
    softmax_rows<<<dim3(SEQ, BATCH), 256>>>();
    gemm_tc<2><<<dim3(DIM / BN, SEQ / BM, BATCH), 128, SMEM_TOTAL>>>(out);
}

// round 17
// speedup vs baseline: 1.6816x; 1.0831x over previous
#include <cuda_runtime.h>
#include <cuda_fp16.h>
#include <math.h>
#include <stdint.h>

// Problem sizes (fixed)
#define BATCH 8
#define SEQ   2048
#define DIM   1024
#define MTOT  (BATCH*SEQ)
#define PLANE (SEQ*DIM)
#define TEN   ((size_t)BATCH*PLANE)

// ---------------- device scratch (no allocations allowed) -------------------
__device__ float  g_scores[(size_t)BATCH * SEQ * SEQ];  // fp32 raw scores (S)
__device__ __half g_Ph[(size_t)BATCH * SEQ * SEQ];      // fp16 UNNORMALIZED exp (E)
__device__ float  g_inv[(size_t)BATCH * SEQ];           // 1/rowsum for PV epilogue
__device__ __half g_Wh[(size_t)3 * DIM * DIM];          // fp16 W^T [n][k]
__device__ __half g_Vh[(size_t)BATCH * DIM * SEQ];      // fp16 V^T [n][k]
__device__ __half g_Xh[(size_t)MTOT * DIM];             // fp16 X
__device__ __half g_Qh[(size_t)MTOT * DIM];             // fp16 Q
__device__ __half g_Kh[(size_t)MTOT * DIM];             // fp16 K

// ---------------- helpers ----------------------------------------------------
__device__ __forceinline__ uint32_t smem_u32(const void* p) {
    uint32_t a;
    asm("{ .reg .u64 t; cvta.to.shared.u64 t, %1; cvt.u32.u64 %0, t; }" : "=r"(a) : "l"(p));
    return a;
}
__device__ __forceinline__ void cp16(uint32_t s, const void* g) {
    asm volatile("cp.async.cg.shared.global [%0], [%1], 16;" :: "r"(s), "l"(g));
}
__device__ __forceinline__ void cp_commit() { asm volatile("cp.async.commit_group;" ::: "memory"); }
template <int N> __device__ __forceinline__ void cp_wait() {
    asm volatile("cp.async.wait_group %0;" :: "n"(N) : "memory");
}
__device__ __forceinline__ void mma_f16(float* c, const uint32_t* a, const uint32_t* b) {
    asm volatile(
        "mma.sync.aligned.m16n8k16.row.col.f32.f16.f16.f32 "
        "{%0,%1,%2,%3}, {%4,%5,%6,%7}, {%8,%9}, {%0,%1,%2,%3};"
        : "+f"(c[0]), "+f"(c[1]), "+f"(c[2]), "+f"(c[3])
        : "r"(a[0]), "r"(a[1]), "r"(a[2]), "r"(a[3]), "r"(b[0]), "r"(b[1]));
}
__device__ __forceinline__ uint32_t ex2_h2(uint32_t a) {   // 2 x 2^x on halves
    uint32_t d;
    asm("ex2.approx.f16x2 %0, %1;" : "=r"(d) : "r"(a));
    return d;
}

// ---------------- GEMM config ------------------------------------------------
#define BM 128
#define BN 128
#define BKH 64                   // K halfs per stage (deepened: fewer syncs/K)
#define PITCH_H 72               // half pitch; word-pitch 36 -> conflict-free frags
#define STAGES 3
#define ASTG (BM*PITCH_H)
#define BSTG (BN*PITCH_H)
#define SMEM_TOTAL (STAGES*(ASTG+BSTG)*2)   // 110,592 B -> 2 CTAs/SM (221KB)

// 128 threads = 4 warps (2 along M x 2 along N), each owns a 64x64 sub-tile.
// MODE 0: QKV  C = Xh * Wh^T
// MODE 1: S    C = Qh * Kh^T (causal blocks, scaled)
// MODE 2: O    C = E  * Vh^T (causal K length; x 1/rowsum in epilogue)
template <int MODE>
__global__ __launch_bounds__(128, 2)
void gemm_tc(float* __restrict__ out)
{
    const int bx = blockIdx.x, by = blockIdx.y, bz = blockIdx.z;
    if (MODE == 1 && bx > by) return;

    const __half *A, *B;
    float *C;
    int lda, ldb, ldc, KT;
    float scale = 1.f;

    if (MODE == 0) {
        A = g_Xh + (size_t)by * BM * DIM;                           lda = DIM;
        B = g_Wh + (size_t)bz * DIM * DIM + (size_t)bx * BN * DIM;  ldb = DIM;
        C = out + (size_t)(1 + bz) * TEN + (size_t)by * BM * DIM + bx * BN; ldc = DIM;
        KT = DIM / BKH;
    } else if (MODE == 1) {
        A = g_Qh + (size_t)bz * PLANE + (size_t)by * BM * DIM;      lda = DIM;
        B = g_Kh + (size_t)bz * PLANE + (size_t)bx * BN * DIM;      ldb = DIM;
        C = g_scores + (size_t)bz * SEQ * SEQ + (size_t)by * BM * SEQ + bx * BN; ldc = SEQ;
        KT = DIM / BKH;
        scale = 0.03125f;   // 1/sqrt(1024)
    } else {
        A = g_Ph + (size_t)bz * SEQ * SEQ + (size_t)by * BM * SEQ;  lda = SEQ;
        B = g_Vh + (size_t)bz * DIM * SEQ + (size_t)bx * BN * SEQ;  ldb = SEQ;
        C = out + (size_t)bz * PLANE + (size_t)by * BM * DIM + bx * BN; ldc = DIM;
        KT = (by + 1) * (BM / BKH);   // (by+1)*2, exact causal coverage
    }

    extern __shared__ __half sm[];
    const uint32_t sb = smem_u32(sm);
    const int tid = threadIdx.x;
    const int lane = tid & 31;
    const int warp = tid >> 5;
    const int warpM = warp & 1;       // 2 warps along M (64 rows)
    const int warpN = warp >> 1;      // 2 warps along N (64 cols)

    float acc[4][8][4];
#pragma unroll
    for (int mt = 0; mt < 4; mt++)
#pragma unroll
        for (int nt = 0; nt < 8; nt++)
#pragma unroll
            for (int i = 0; i < 4; i++) acc[mt][nt][i] = 0.f;

    // Stage tile: rows x 64 halfs; 8 x 16B chunks per row.
    auto load_stage = [&](int st, int k0) {
        const uint32_t sA = sb + (uint32_t)(st * ASTG) * 2;
        const uint32_t sB = sb + (uint32_t)((STAGES * ASTG) + st * BSTG) * 2;
#pragma unroll
        for (int i = 0; i < 8; i++) {              // A: 128 rows x 8 chunks = 1024
            int ci = tid + i * 128;
            int r = ci >> 3, ch = ci & 7;
            cp16(sA + (uint32_t)(r * PITCH_H + ch * 8) * 2, A + (size_t)r * lda + k0 + ch * 8);
        }
#pragma unroll
        for (int i = 0; i < 8; i++) {              // B: 128 rows x 8 chunks
            int ci = tid + i * 128;
            int r = ci >> 3, ch = ci & 7;
            cp16(sB + (uint32_t)(r * PITCH_H + ch * 8) * 2, B + (size_t)r * ldb + k0 + ch * 8);
        }
    };

#pragma unroll
    for (int p = 0; p < STAGES - 1; p++) {
        load_stage(p, p * BKH);
        cp_commit();
    }

    for (int it = 0; it < KT; ++it) {
        cp_wait<STAGES - 2>();
        __syncthreads();

        const int nx = it + STAGES - 1;
        if (nx < KT) load_stage(nx % STAGES, nx * BKH);
        cp_commit();

        const int s = it % STAGES;
        const __half* sAf = sm + s * ASTG;
        const __half* sBf = sm + STAGES * ASTG + s * BSTG;

#pragma unroll
        for (int k16 = 0; k16 < BKH / 16; k16++) {
            const int ch = k16 * 16 + 2 * (lane & 3);
            uint32_t af[4][4];
            uint32_t bf[8][2];
            const int r0 = warpM * 64 + (lane >> 2);
#pragma unroll
            for (int mt = 0; mt < 4; mt++) {
                const int rr = r0 + mt * 16;
                af[mt][0] = *(const uint32_t*)(sAf + rr * PITCH_H + ch);
                af[mt][1] = *(const uint32_t*)(sAf + (rr + 8) * PITCH_H + ch);
                af[mt][2] = *(const uint32_t*)(sAf + rr * PITCH_H + ch + 8);
                af[mt][3] = *(const uint32_t*)(sAf + (rr + 8) * PITCH_H + ch + 8);
            }
            const int n0 = warpN * 64 + (lane >> 2);
#pragma unroll
            for (int nt = 0; nt < 8; nt++) {
                const int nn = n0 + nt * 8;
                bf[nt][0] = *(const uint32_t*)(sBf + nn * PITCH_H + ch);
                bf[nt][1] = *(const uint32_t*)(sBf + nn * PITCH_H + ch + 8);
            }
#pragma unroll
            for (int mt = 0; mt < 4; mt++)
#pragma unroll
                for (int nt = 0; nt < 8; nt++)
                    mma_f16(acc[mt][nt], af[mt], bf[nt]);
        }
        __syncthreads();
    }

    // ---- epilogue ----
    const int rbase = warpM * 64 + (lane >> 2);
    const int cbase = warpN * 64 + 2 * (lane & 3);
#pragma unroll
    for (int mt = 0; mt < 4; mt++) {
        const int row = rbase + mt * 16;
        float s0 = scale, s1 = scale;
        if (MODE == 2) {   // fold softmax 1/rowsum into the PV epilogue
            const float* inv = g_inv + (size_t)bz * SEQ + by * BM;
            s0 = inv[row];
            s1 = inv[row + 8];
        }
#pragma unroll
        for (int nt = 0; nt < 8; nt++) {
            const int col = cbase + nt * 8;
            float2 v0 = {acc[mt][nt][0] * s0, acc[mt][nt][1] * s0};
            float2 v1 = {acc[mt][nt][2] * s1, acc[mt][nt][3] * s1};
            *(float2*)(C + (size_t)row * ldc + col)       = v0;
            *(float2*)(C + (size_t)(row + 8) * ldc + col) = v1;

            if (MODE == 0 && bz < 2) {   // emit fp16 Q / K for the score GEMM
                __half* T = (bz == 0 ? g_Qh : g_Kh) +
                            (size_t)(by * BM + row) * DIM + bx * BN + col;
                *(__half2*)T = __floats2half2_rn(v0.x, v0.y);
                *(__half2*)(T + (size_t)8 * DIM) = __floats2half2_rn(v1.x, v1.y);
            }
        }
    }
}

// ---------------- producers --------------------------------------------------
__global__ __launch_bounds__(256)
void cvt_x(const float* __restrict__ X)
{
    size_t i = ((size_t)blockIdx.x * 256 + threadIdx.x) * 4;
    float4 v = *(const float4*)(X + i);
    *(__half2*)(g_Xh + i)     = __floats2half2_rn(v.x, v.y);
    *(__half2*)(g_Xh + i + 2) = __floats2half2_rn(v.z, v.w);
}

__global__ __launch_bounds__(256)
void transpose_w(const float* __restrict__ Wq, const float* __restrict__ Wk,
                 const float* __restrict__ Wv)
{
    __shared__ float t[32][33];
    const int w = blockIdx.z;
    const float* W = (w == 0) ? Wq : (w == 1) ? Wk : Wv;
    __half* Wh = g_Wh + (size_t)w * DIM * DIM;
    const int n0 = blockIdx.x * 32, k0 = blockIdx.y * 32;
    const int tx = threadIdx.x & 31, ty = threadIdx.x >> 5;
#pragma unroll
    for (int j = 0; j < 4; j++)
        t[ty * 4 + j][tx] = W[(size_t)(k0 + ty * 4 + j) * DIM + n0 + tx];
    __syncthreads();
#pragma unroll
    for (int j = 0; j < 4; j++)
        Wh[(size_t)(n0 + ty * 4 + j) * DIM + k0 + tx] = __float2half_rn(t[tx][ty * 4 + j]);
}

__global__ __launch_bounds__(256)
void transpose_v(const float* __restrict__ out)
{
    __shared__ float t[32][33];
    const int b = blockIdx.z;
    const float* V = out + 3 * TEN + (size_t)b * PLANE;   // [S][D] fp32
    __half* Vh = g_Vh + (size_t)b * DIM * SEQ;            // [D][S] fp16
    const int s0 = blockIdx.x * 32, a0 = blockIdx.y * 32;
    const int tx = threadIdx.x & 31, ty = threadIdx.x >> 5;
#pragma unroll
    for (int j = 0; j < 4; j++)
        t[ty * 4 + j][tx] = V[(size_t)(s0 + ty * 4 + j) * DIM + a0 + tx];
    __syncthreads();
#pragma unroll
    for (int j = 0; j < 4; j++)
        Vh[(size_t)(a0 + ty * 4 + j) * SEQ + s0 + tx] = __float2half_rn(t[tx][ty * 4 + j]);
}

// ---------------- softmax: E = exp(s - max) in fp16 (unnormalized),
//                  1/rowsum -> g_inv (applied in PV epilogue) -----------------
#define LOG2E 1.44269504088896340736f
__global__ __launch_bounds__(256)
void softmax_rows()
{
    __shared__ float row[SEQ];
    __shared__ float red[8];
    const int q = blockIdx.x, b = blockIdx.y, tid = threadIdx.x;
    const int lane = tid & 31, warp = tid >> 5;
    const float* Srow = g_scores + (size_t)b * SEQ * SEQ + (size_t)q * SEQ;
    __half* Prow = g_Ph + (size_t)b * SEQ * SEQ + (size_t)q * SEQ;
    const int L = q + 1;
    const int kend = ((q >> 7) + 1) << 7;
    const int L4 = L >> 2;

    float mx = -INFINITY;
    const float4* S4 = (const float4*)Srow;
    for (int i = tid; i < L4; i += 256) {
        float4 v = S4[i];
        *(float4*)&row[i * 4] = v;
        mx = fmaxf(fmaxf(mx, fmaxf(v.x, v.y)), fmaxf(v.z, v.w));
    }
    if (L4 * 4 + tid < L) {
        float v = Srow[L4 * 4 + tid];
        row[L4 * 4 + tid] = v;
        mx = fmaxf(mx, v);
    }
#pragma unroll
    for (int o = 16; o > 0; o >>= 1) mx = fmaxf(mx, __shfl_xor_sync(~0u, mx, o));
    if (lane == 0) red[warp] = mx;
    __syncthreads();
    mx = red[0];
#pragma unroll
    for (int w2 = 1; w2 < 8; w2++) mx = fmaxf(mx, red[w2]);
    __syncthreads();

    // single exp pass: y = (s-mx)*log2e <= 0, 2^y via f16x2 MUFU (2 per op)
    float sum = 0.f;
    for (int i = tid; i < L4; i += 256) {
        float4 v = *(float4*)&row[i * 4];
        __half2 y0 = __floats2half2_rn((v.x - mx) * LOG2E, (v.y - mx) * LOG2E);
        __half2 y1 = __floats2half2_rn((v.z - mx) * LOG2E, (v.w - mx) * LOG2E);
        uint32_t e0 = ex2_h2(*(uint32_t*)&y0);
        uint32_t e1 = ex2_h2(*(uint32_t*)&y1);
        *(uint32_t*)(Prow + i * 4)     = e0;
        *(uint32_t*)(Prow + i * 4 + 2) = e1;
        __half2 h0 = *(__half2*)&e0;
        __half2 h1 = *(__half2*)&e1;
        sum += __low2float(h0) + __high2float(h0) + __low2float(h1) + __high2float(h1);
    }
    if (L4 * 4 + tid < L) {
        const int j = L4 * 4 + tid;
        __half2 y = __floats2half2_rn((row[j] - mx) * LOG2E, -100.f);
        uint32_t e = ex2_h2(*(uint32_t*)&y);
        __half2 h = *(__half2*)&e;
        Prow[j] = __low2half(h);
        sum += __low2float(h);
    }
#pragma unroll
    for (int o = 16; o > 0; o >>= 1) sum += __shfl_xor_sync(~0u, sum, o);
    if (lane == 0) red[warp] = sum;
    __syncthreads();
    sum = 0.f;
#pragma unroll
    for (int w2 = 0; w2 < 8; w2++) sum += red[w2];
    if (tid == 0) g_inv[(size_t)b * SEQ + q] = 1.f / sum;

    for (int i = L + tid; i < kend; i += 256) Prow[i] = __ushort_as_half((unsigned short)0);
}

// ---------------- launch -----------------------------------------------------
extern "C" void kernel_launch(void* const* d_in, const int* in_sizes, int n_in,
                              void* d_out, int out_size)
{
    const float* X  = (const float*)d_in[0];
    const float* Wq = (const float*)d_in[1];
    const float* Wk = (const float*)d_in[2];
    const float* Wv = (const float*)d_in[3];
    float* out = (float*)d_out;

    static bool attr_done = false;
    if (!attr_done) {
        cudaFuncSetAttribute(gemm_tc<0>, cudaFuncAttributeMaxDynamicSharedMemorySize, SMEM_TOTAL);
        cudaFuncSetAttribute(gemm_tc<1>, cudaFuncAttributeMaxDynamicSharedMemorySize, SMEM_TOTAL);
        cudaFuncSetAttribute(gemm_tc<2>, cudaFuncAttributeMaxDynamicSharedMemorySize, SMEM_TOTAL);
        attr_done = true;
    }

    cvt_x<<<(MTOT * (size_t)DIM) / (256 * 4), 256>>>(X);
    transpose_w<<<dim3(DIM / 32, DIM / 32, 3), 256>>>(Wq, Wk, Wv);
    gemm_tc<0><<<dim3(DIM / BN, MTOT / BM, 3), 128, SMEM_TOTAL>>>(out);
    transpose_v<<<dim3(SEQ / 32, DIM / 32, BATCH), 256>>>(out);
    gemm_tc<1><<<dim3(SEQ / BN, SEQ / BM, BATCH), 128, SMEM_TOTAL>>>(out);
    softmax_rows<<<dim3(SEQ, BATCH), 256>>>();
    gemm_tc<2><<<dim3(DIM / BN, SEQ / BM, BATCH), 128, SMEM_TOTAL>>>(out);
}